// round 3
// baseline (speedup 1.0000x reference)
#include <cuda_runtime.h>
#include <math.h>

// ---------------------------------------------------------------------------
// AliasFreeConv: modulated 3x3 conv (demodulated) + 2x up (12-tap separable)
// + leaky relu + 2x down (12-tap separable).  B=8, C=512->512, 64x64 input.
//
// Restructure: w[b,co,ci,k] = conv_w * (wscale*s[b,ci]) * demod[b,co]
//   -> scale input per (b,ci), conv with SHARED conv_w, scale output per (b,co)
// Conv mainloop uses packed fp32 (fma.rn.f32x2): pair of couts per 64-bit acc.
// ---------------------------------------------------------------------------

#define BATCH   8
#define CH      512
#define HW      64
#define OHW     62
#define BC      (BATCH * CH)  // 4096
#define TAPS    12

#define LIN_SCALE 0.04419417382415922f     // 1/sqrt(512)
#define WSCALE    0.014731391274719738f    // 1/sqrt(512*9)
#define NEG_SLOPE 0.2f
#define LRELU_SCALE 1.4142135623730951f
#define EPS_F   1e-8f

typedef unsigned long long u64;

__device__ __forceinline__ u64 pk2(float lo, float hi) {
    u64 r; asm("mov.b64 %0,{%1,%2};" : "=l"(r) : "f"(lo), "f"(hi)); return r;
}
__device__ __forceinline__ u64 ffma2(u64 a, u64 b, u64 c) {
    u64 d; asm("fma.rn.f32x2 %0,%1,%2,%3;" : "=l"(d) : "l"(a), "l"(b), "l"(c)); return d;
}
__device__ __forceinline__ float2 upk2(u64 a) {
    float2 f; asm("mov.b64 {%0,%1},%2;" : "=f"(f.x), "=f"(f.y) : "l"(a)); return f;
}

// ------------------------- scratch (device globals) ------------------------
__device__ float g_sscale[BC];
__device__ float g_dscale[BC];
__device__ float g_wsq[CH * CH];
__device__ float g_conv[(size_t)BC * OHW * OHW];     // [bc][62][62]
__device__ float g_up2 [(size_t)BC * 128 * 128];     // [bc][128][128] (lrelu'd)

// ------------------------------ modulation ---------------------------------
__global__ void mod_kernel(const float* __restrict__ style,
                           const float* __restrict__ mod_w,
                           const float* __restrict__ mod_b)
{
    int b  = blockIdx.x;
    int ci = threadIdx.x;
    const float* st = style + b * CH;
    const float* mw = mod_w + ci * CH;
    float acc = 0.f;
    for (int k = 0; k < CH; k++) acc += st[k] * mw[k];
    float s = acc * LIN_SCALE + mod_b[ci];
    g_sscale[b * CH + ci] = WSCALE * s;
}

__global__ void wsq_kernel(const float* __restrict__ conv_w)
{
    int id = blockIdx.x * blockDim.x + threadIdx.x;
    if (id >= CH * CH) return;
    int co = id & (CH - 1);
    int ci = id >> 9;
    const float* w = conv_w + (size_t)co * CH * 9 + ci * 9;
    float acc = 0.f;
#pragma unroll
    for (int k = 0; k < 9; k++) acc += w[k] * w[k];
    g_wsq[ci * CH + co] = acc;
}

__global__ void demod_kernel()
{
    int id = blockIdx.x * blockDim.x + threadIdx.x;
    if (id >= BATCH * CH) return;
    int co = id & (CH - 1);
    int b  = id >> 9;
    float acc = 0.f;
    for (int ci = 0; ci < CH; ci++) {
        float ss = g_sscale[b * CH + ci];
        acc += g_wsq[ci * CH + co] * (ss * ss);
    }
    g_dscale[id] = 1.0f / sqrtf(acc + EPS_F);
}

// ------------------------------- conv --------------------------------------
// Block: 64 couts x (16x16 px).  Thread: 8 couts (4 f32x2 pairs) x 8 px.
#define CI_CHUNK 8

__global__ __launch_bounds__(256)
void conv_kernel(const float* __restrict__ x,
                 const float* __restrict__ conv_w,
                 const float* __restrict__ act_b)
{
    __shared__ float  xs[CI_CHUNK][18][20];        // padded rows: 16B-aligned
    __shared__ float2 ws2[CI_CHUNK * 9][33];       // [ck][cout-pair], padded

    int t   = threadIdx.x;
    int ox0 = blockIdx.x * 16;
    int oy0 = blockIdx.y * 16;
    int z   = blockIdx.z;              // b*8 + coblk
    int b   = z >> 3;
    int co0 = (z & 7) * 64;

    int cg   = t >> 5;                 // 0..7 (constant per warp)
    int pxg  = t & 31;
    int cop0 = cg * 4;                 // first cout-pair index (of 32)
    int row  = pxg >> 1;               // 0..15
    int col0 = (pxg & 1) * 8;          // 0 or 8

    u64 acc[4][8];
#pragma unroll
    for (int ip = 0; ip < 4; ip++)
#pragma unroll
        for (int j = 0; j < 8; j++) acc[ip][j] = 0ULL;

    const float* xb  = x + (size_t)b * CH * HW * HW;
    const float* ssb = g_sscale + b * CH;

    for (int ci0 = 0; ci0 < CH; ci0 += CI_CHUNK) {
        __syncthreads();
        // input tile (scaled per channel)
        for (int e = t; e < CI_CHUNK * 18 * 18; e += 256) {
            int cl  = e / 324;
            int rem = e - cl * 324;
            int r   = rem / 18;
            int c   = rem - r * 18;
            int iy = oy0 + r, ix = ox0 + c;
            float v = 0.f;
            if (iy < HW && ix < HW)
                v = xb[(size_t)(ci0 + cl) * (HW * HW) + iy * HW + ix] * ssb[ci0 + cl];
            xs[cl][r][c] = v;
        }
        // weight pairs: ws2[ck][p] = (w[co0+2p], w[co0+2p+1]) for ck = ci*9+k
        for (int e = t; e < 32 * CI_CHUNK * 9; e += 256) {
            int cop = e & 31;
            int ck  = e >> 5;
            int ci  = ck / 9;
            int k   = ck - ci * 9;
            const float* wb = conv_w + (size_t)(co0 + 2 * cop) * (CH * 9)
                            + (ci0 + ci) * 9 + k;
            ws2[ck][cop] = make_float2(wb[0], wb[CH * 9]);
        }
        __syncthreads();

#pragma unroll 1
        for (int ci = 0; ci < CI_CHUNK; ci++) {
#pragma unroll
            for (int kh = 0; kh < 3; kh++) {
                const float* xr = &xs[ci][row + kh][col0];
                float4 v0 = *(const float4*)(xr);
                float4 v1 = *(const float4*)(xr + 4);
                float2 v2 = *(const float2*)(xr + 8);
                float xv[10] = {v0.x, v0.y, v0.z, v0.w,
                                v1.x, v1.y, v1.z, v1.w,
                                v2.x, v2.y};
                u64 xd[10];
#pragma unroll
                for (int p = 0; p < 10; p++) xd[p] = pk2(xv[p], xv[p]);
#pragma unroll
                for (int kw = 0; kw < 3; kw++) {
                    int ck = ci * 9 + kh * 3 + kw;
                    u64 w0 = *(const u64*)&ws2[ck][cop0 + 0];
                    u64 w1 = *(const u64*)&ws2[ck][cop0 + 1];
                    u64 w2 = *(const u64*)&ws2[ck][cop0 + 2];
                    u64 w3 = *(const u64*)&ws2[ck][cop0 + 3];
#pragma unroll
                    for (int j = 0; j < 8; j++) {
                        u64 xp = xd[kw + j];
                        acc[0][j] = ffma2(xp, w0, acc[0][j]);
                        acc[1][j] = ffma2(xp, w1, acc[1][j]);
                        acc[2][j] = ffma2(xp, w2, acc[2][j]);
                        acc[3][j] = ffma2(xp, w3, acc[3][j]);
                    }
                }
            }
        }
    }

    // epilogue: demod scale + bias  (pair halves are two adjacent couts)
    int oy = oy0 + row;
    if (oy < OHW) {
#pragma unroll
        for (int ip = 0; ip < 4; ip++) {
            int c0 = co0 + 2 * (cop0 + ip);
            float ds0 = g_dscale[b * CH + c0];
            float ds1 = g_dscale[b * CH + c0 + 1];
            float b0  = act_b[c0];
            float b1  = act_b[c0 + 1];
            float* p0 = g_conv + ((size_t)b * CH + c0) * (OHW * OHW) + oy * OHW;
            float* p1 = p0 + OHW * OHW;
#pragma unroll
            for (int j = 0; j < 8; j++) {
                int ox = ox0 + col0 + j;
                if (ox < OHW) {
                    float2 v = upk2(acc[ip][j]);
                    p0[ox] = v.x * ds0 + b0;
                    p1[ox] = v.y * ds1 + b1;
                }
            }
        }
    }
}

// ----------------------------- fused up pass -------------------------------
// block per image: conv[62][62] -> (up_h) [62][128] -> (up_v) [128][128],
// lrelu applied on write.  All intermediates in smem.
__global__ __launch_bounds__(256)
void up_fused_kernel(const float* __restrict__ f)
{
    __shared__ float sA[OHW * OHW];     // 15376 B
    __shared__ float sB[OHW * 128];     // 31744 B
    int bc = blockIdx.x;
    int t  = threadIdx.x;

    float fc[TAPS];
#pragma unroll
    for (int i = 0; i < TAPS; i++) fc[i] = f[i];

    const float* src = g_conv + (size_t)bc * (OHW * OHW);
    for (int e = t; e < OHW * OHW; e += 256) sA[e] = src[e];
    __syncthreads();

    // horizontal up: up=2, pad0=8, gain 2
    for (int e = t; e < OHW * 128; e += 256) {
        int o = e & 127;
        int y = e >> 7;
        const float* rowp = sA + y * OHW;
        float acc = 0.f;
#pragma unroll
        for (int tp = 0; tp < TAPS; tp++) {
            int i = o + tp - 8;
            if (i >= 0 && !(i & 1)) {
                int ii = i >> 1;
                if (ii < OHW) acc += fc[TAPS - 1 - tp] * rowp[ii];
            }
        }
        sB[e] = acc * 2.0f;
    }
    __syncthreads();

    // vertical up + lrelu, write g_up2
    float* dst = g_up2 + (size_t)bc * (128 * 128);
    for (int e = t; e < 128 * 128; e += 256) {
        int xcol = e & 127;
        int oy   = e >> 7;
        float acc = 0.f;
#pragma unroll
        for (int tp = 0; tp < TAPS; tp++) {
            int i = oy + tp - 8;
            if (i >= 0 && !(i & 1)) {
                int ii = i >> 1;
                if (ii < OHW) acc += fc[TAPS - 1 - tp] * sB[ii * 128 + xcol];
            }
        }
        float v = acc * 2.0f;
        dst[e] = (v >= 0.f ? v : NEG_SLOPE * v) * LRELU_SCALE;
    }
}

// ----------------------------- fused down pass -----------------------------
// block per image: up2[128][128] -> (down_h) [128][64] -> (down_v) [64][64]
__global__ __launch_bounds__(256)
void down_fused_kernel(const float* __restrict__ f,
                       float* __restrict__ out)
{
    __shared__ float sC[128 * 64];      // 32768 B
    int bc = blockIdx.x;
    int t  = threadIdx.x;

    float fc[TAPS];
#pragma unroll
    for (int i = 0; i < TAPS; i++) fc[i] = f[i];

    const float* src = g_up2 + (size_t)bc * (128 * 128);
    // horizontal down: down=2, pad0=5
    for (int e = t; e < 128 * 64; e += 256) {
        int xo = e & 63;
        int y  = e >> 6;
        const float* rowp = src + y * 128;
        float acc = 0.f;
#pragma unroll
        for (int tp = 0; tp < TAPS; tp++) {
            int i = 2 * xo + tp - 5;
            if (i >= 0 && i < 128) acc += fc[TAPS - 1 - tp] * rowp[i];
        }
        sC[e] = acc;
    }
    __syncthreads();

    // vertical down -> out
    float* dst = out + (size_t)bc * (64 * 64);
    for (int e = t; e < 64 * 64; e += 256) {
        int xcol = e & 63;
        int oy   = e >> 6;
        float acc = 0.f;
#pragma unroll
        for (int tp = 0; tp < TAPS; tp++) {
            int i = 2 * oy + tp - 5;
            if (i >= 0 && i < 128) acc += fc[TAPS - 1 - tp] * sC[i * 64 + xcol];
        }
        dst[e] = acc;
    }
}

// ------------------------------ launcher -----------------------------------
extern "C" void kernel_launch(void* const* d_in, const int* in_sizes, int n_in,
                              void* d_out, int out_size)
{
    const float* x        = (const float*)d_in[0];
    const float* style    = (const float*)d_in[1];
    const float* mod_w    = (const float*)d_in[2];
    const float* mod_b    = (const float*)d_in[3];
    const float* conv_w   = (const float*)d_in[4];
    const float* act_b    = (const float*)d_in[5];
    const float* up_filt  = (const float*)d_in[6];
    const float* dn_filt  = (const float*)d_in[7];
    float* out = (float*)d_out;

    mod_kernel<<<BATCH, CH>>>(style, mod_w, mod_b);
    wsq_kernel<<<(CH * CH) / 256, 256>>>(conv_w);
    demod_kernel<<<(BATCH * CH + 127) / 128, 128>>>();

    dim3 cgrid(4, 4, BATCH * 8);
    conv_kernel<<<cgrid, 256>>>(x, conv_w, act_b);

    up_fused_kernel  <<<BC, 256>>>(up_filt);
    down_fused_kernel<<<BC, 256>>>(dn_filt, out);
}